// round 1
// baseline (speedup 1.0000x reference)
#include <cuda_runtime.h>
#include <math.h>
#include <stdint.h>

#define NN 4096
#define DD 128
#define BK 32
#define LDA 132   // padded leading dim (floats) for K-major smem tiles

// ---------------- device-global scratch (no allocations allowed) ----------------
__device__ float    g_negsum[NN];
__device__ float    g_poslog[NN];
__device__ int      g_poscnt[NN];
__device__ unsigned g_minsimi[NN];   // float bits of min positive simi (positive floats: bit order == value order)
__device__ unsigned g_maxdist_u;
__device__ unsigned g_maxedge_u;
__device__ unsigned g_minedge_u;
__device__ float    g_loss;

// monotonic key mapping for signed-float atomic max/min on unsigned
__device__ __forceinline__ unsigned fkey(float f) {
    unsigned b = __float_as_uint(f);
    return (b & 0x80000000u) ? ~b : (b | 0x80000000u);
}
__device__ __forceinline__ float fkey_inv(unsigned k) {
    return (k & 0x80000000u) ? __uint_as_float(k ^ 0x80000000u)
                             : __uint_as_float(~k);
}

// ---------------- kernel 1: zero scratch + copy x to output ----------------
__global__ void k_init(const float4* __restrict__ x4, float4* __restrict__ out4) {
    int i = blockIdx.x * 256 + threadIdx.x;
    if (i < NN * DD / 4) out4[i] = x4[i];
    if (i < NN) {
        g_negsum[i] = 0.f;
        g_poslog[i] = 0.f;
        g_poscnt[i] = 0;
        g_minsimi[i] = 0x7F800000u;  // +inf
    }
    if (i == 0) {
        g_maxdist_u = 0u;
        g_maxedge_u = 0u;            // key 0 == smallest possible
        g_minedge_u = 0xFFFFFFFFu;   // key max
        g_loss = 0.f;
    }
}

// ---------------- kernel 2: fused SGEMM + epilogue ----------------
// mink[i][j] = sum_d eta_d * x[i][d] * x[j][d], eta_0 = -1 (negate col 0 of B side).
__global__ __launch_bounds__(256, 2)
void k_main(const float* __restrict__ x, const int* __restrict__ adj,
            float* __restrict__ dist) {
    __shared__ float sA[BK][LDA];
    __shared__ float sB[BK][LDA];

    const int tid = threadIdx.x;
    const int tx = tid & 15;       // 0..15 -> 8 cols each
    const int ty = tid >> 4;       // 0..15 -> 8 rows each
    const int rowBase = blockIdx.y * 128;
    const int colBase = blockIdx.x * 128;

    const int f4 = tid & 7;        // which float4 along K (0..7)
    const int rb = tid >> 3;       // base row 0..31

    float acc[8][8];
#pragma unroll
    for (int i = 0; i < 8; i++)
#pragma unroll
        for (int j = 0; j < 8; j++) acc[i][j] = 0.f;

    for (int kt = 0; kt < 4; ++kt) {
        // ---- load A/B tiles, transposed to K-major with eta applied to B col 0 ----
#pragma unroll
        for (int r4 = 0; r4 < 4; ++r4) {
            int row = rb + 32 * r4;
            float4 va = *reinterpret_cast<const float4*>(
                &x[(size_t)(rowBase + row) * DD + kt * BK + f4 * 4]);
            float4 vb = *reinterpret_cast<const float4*>(
                &x[(size_t)(colBase + row) * DD + kt * BK + f4 * 4]);
            if (kt == 0 && f4 == 0) vb.x = -vb.x;   // Minkowski sign on d==0
            int k0 = f4 * 4;
            sA[k0 + 0][row] = va.x; sA[k0 + 1][row] = va.y;
            sA[k0 + 2][row] = va.z; sA[k0 + 3][row] = va.w;
            sB[k0 + 0][row] = vb.x; sB[k0 + 1][row] = vb.y;
            sB[k0 + 2][row] = vb.z; sB[k0 + 3][row] = vb.w;
        }
        __syncthreads();

        // ---- 8x8 outer-product micro-kernel ----
#pragma unroll 8
        for (int k = 0; k < BK; ++k) {
            float a[8], b[8];
            *reinterpret_cast<float4*>(&a[0]) = *reinterpret_cast<const float4*>(&sA[k][ty * 8]);
            *reinterpret_cast<float4*>(&a[4]) = *reinterpret_cast<const float4*>(&sA[k][ty * 8 + 4]);
            *reinterpret_cast<float4*>(&b[0]) = *reinterpret_cast<const float4*>(&sB[k][tx * 8]);
            *reinterpret_cast<float4*>(&b[4]) = *reinterpret_cast<const float4*>(&sB[k][tx * 8 + 4]);
#pragma unroll
            for (int i = 0; i < 8; i++)
#pragma unroll
                for (int j = 0; j < 8; j++) acc[i][j] += a[i] * b[j];
        }
        __syncthreads();
    }

    // ---- fused epilogue ----
    float locMaxD = 0.f;                      // dist >= 0
    float locMaxE = -INFINITY, locMinE = INFINITY;

#pragma unroll
    for (int i = 0; i < 8; i++) {
        int gRow = rowBase + ty * 8 + i;
        const int* arow = &adj[(size_t)gRow * NN + colBase + tx * 8];
        int4 aj0 = *reinterpret_cast<const int4*>(arow);
        int4 aj1 = *reinterpret_cast<const int4*>(arow + 4);
        int av[8] = {aj0.x, aj0.y, aj0.z, aj0.w, aj1.x, aj1.y, aj1.z, aj1.w};

        float dv[8];
        float neg = 0.f, plog = 0.f, msimi = INFINITY;
        int pcnt = 0;
#pragma unroll
        for (int j = 0; j < 8; j++) {
            float c = acc[i][j];
            float theta = fmaxf(-c, 1.0f + 1e-7f);
            float sq = sqrtf((theta - 1.0f) * (theta + 1.0f));
            float ac = __logf(theta + sq);           // acosh(theta)
            float d = fminf(ac * ac, 50.0f);
            dv[j] = d;
            locMaxD = fmaxf(locMaxD, d);
            float simi = fmaxf(__expf(-d), 1e-15f);
            if (av[j] != 0) {
                pcnt++;
                plog += fmaxf(-d, -34.538776394910684f);  // log(max(exp(-d),1e-15))
                msimi = fminf(msimi, simi);
                locMaxE = fmaxf(locMaxE, c);
                locMinE = fminf(locMinE, c);
            } else {
                neg += simi;
                locMaxE = fmaxf(locMaxE, 0.f);   // edge_inner = inner*posf -> 0
                locMinE = fminf(locMinE, 0.f);
            }
        }
        float* drow = &dist[(size_t)gRow * NN + colBase + tx * 8];
        *reinterpret_cast<float4*>(drow)     = make_float4(dv[0], dv[1], dv[2], dv[3]);
        *reinterpret_cast<float4*>(drow + 4) = make_float4(dv[4], dv[5], dv[6], dv[7]);

        // reduce the per-row partials across the 16 tx lanes (xor stays in 16-group)
#pragma unroll
        for (int off = 1; off < 16; off <<= 1) {
            neg  += __shfl_xor_sync(0xffffffffu, neg,  off);
            plog += __shfl_xor_sync(0xffffffffu, plog, off);
            pcnt += __shfl_xor_sync(0xffffffffu, pcnt, off);
            msimi = fminf(msimi, __shfl_xor_sync(0xffffffffu, msimi, off));
        }
        if (tx == 0) {
            atomicAdd(&g_negsum[gRow], neg);
            atomicAdd(&g_poslog[gRow], plog);
            atomicAdd(&g_poscnt[gRow], pcnt);
            atomicMin(&g_minsimi[gRow], __float_as_uint(msimi));
        }
    }

    // block-wide reduce of the 3 scalars
#pragma unroll
    for (int off = 16; off > 0; off >>= 1) {
        locMaxD = fmaxf(locMaxD, __shfl_xor_sync(0xffffffffu, locMaxD, off));
        locMaxE = fmaxf(locMaxE, __shfl_xor_sync(0xffffffffu, locMaxE, off));
        locMinE = fminf(locMinE, __shfl_xor_sync(0xffffffffu, locMinE, off));
    }
    __shared__ float red[3][8];
    int w = tid >> 5, l = tid & 31;
    if (l == 0) { red[0][w] = locMaxD; red[1][w] = locMaxE; red[2][w] = locMinE; }
    __syncthreads();
    if (tid == 0) {
        float md = red[0][0], me = red[1][0], mn = red[2][0];
#pragma unroll
        for (int i = 1; i < 8; i++) {
            md = fmaxf(md, red[0][i]);
            me = fmaxf(me, red[1][i]);
            mn = fminf(mn, red[2][i]);
        }
        atomicMax(&g_maxdist_u, fkey(md));
        atomicMax(&g_maxedge_u, fkey(me));
        atomicMin(&g_minedge_u, fkey(mn));
    }
}

// ---------------- kernel 3: per-row loss finalize ----------------
__global__ void k_finalize(const float* __restrict__ dist, const int* __restrict__ adj) {
    int row = blockIdx.x;
    int cnt = g_poscnt[row];
    if (cnt == 0) return;
    float ns = g_negsum[row];
    float msimi = __uint_as_float(g_minsimi[row]);
    bool clampFree = (ns > 0.f) && (msimi >= 1e-15f * ns);
    if (clampFree) {
        if (threadIdx.x == 0) {
            float li = -(g_poslog[row] - (float)cnt * __logf(ns));
            atomicAdd(&g_loss, li);
        }
        return;
    }
    // rare fallback: rescan row with exact clamping
    float part = 0.f;
    for (int j = threadIdx.x; j < NN; j += blockDim.x) {
        if (adj[(size_t)row * NN + j]) {
            float d = dist[(size_t)row * NN + j];
            float simi = fmaxf(__expf(-d), 1e-15f);
            float ratio = fmaxf(simi / ns, 1e-15f);
            part += __logf(ratio);
        }
    }
#pragma unroll
    for (int off = 16; off > 0; off >>= 1)
        part += __shfl_xor_sync(0xffffffffu, part, off);
    __shared__ float sred[8];
    int w = threadIdx.x >> 5, l = threadIdx.x & 31;
    if (l == 0) sred[w] = part;
    __syncthreads();
    if (threadIdx.x == 0) {
        float s = 0.f;
        for (int i = 0; i < (int)blockDim.x / 32; i++) s += sred[i];
        atomicAdd(&g_loss, -s);
    }
}

// ---------------- kernel 4: write the 4 scalar outputs ----------------
__global__ void k_scalars(float* __restrict__ outsc) {
    outsc[0] = g_loss;
    outsc[1] = fkey_inv(g_maxdist_u);
    outsc[2] = fkey_inv(g_maxedge_u);
    outsc[3] = fkey_inv(g_minedge_u);
}

// ---------------- launch ----------------
extern "C" void kernel_launch(void* const* d_in, const int* in_sizes, int n_in,
                              void* d_out, int out_size) {
    const float* x  = (const float*)d_in[0];   // [N, D] fp32
    const int* adj  = (const int*)d_in[1];     // [N, N] int32
    float* out = (float*)d_out;

    // output layout: x (N*D) | dist (N*N) | loss | max(dist) | max(edge) | min(edge)
    size_t distOff = (size_t)out_size - 4 - (size_t)NN * NN;
    float* dist  = out + distOff;
    float* outsc = out + ((size_t)out_size - 4);

    k_init<<<(NN * DD / 4 + 255) / 256, 256>>>((const float4*)x, (float4*)out);
    dim3 grid(NN / 128, NN / 128);
    k_main<<<grid, 256>>>(x, adj, dist);
    k_finalize<<<NN, 256>>>(dist, adj);
    k_scalars<<<1, 1>>>(outsc);
}

// round 4
// speedup vs baseline: 1.0535x; 1.0535x over previous
#include <cuda_runtime.h>
#include <cuda_bf16.h>
#include <math.h>
#include <stdint.h>

#define NN 4096
#define DD 128

// ---- dynamic smem layout (bytes) ----
#define SM_X0R    0            // 128 floats
#define SM_X0C    512          // 128 floats
#define SM_A      2048         // A2: 128 rows x 256 bf16 ([hi|lo]), 64 KB
#define SM_B      (2048 + 65536)   // B2: 128 cols x 256 bf16 ([lo|hi]), 64 KB
#define SM_D      2048         // reuse tile region after MMA: 128 x 132 fp32
#define SM_TOTAL  (2048 + 131072)
#define SD_LD     132

// ---------------- device-global scratch ----------------
__device__ float    g_negsum[NN];
__device__ float    g_poslog[NN];
__device__ int      g_poscnt[NN];
__device__ unsigned g_minsimi[NN];
__device__ unsigned g_maxdist_u;
__device__ unsigned g_maxedge_u;
__device__ unsigned g_minedge_u;
__device__ float    g_loss;

__device__ __forceinline__ unsigned fkey(float f) {
    unsigned b = __float_as_uint(f);
    return (b & 0x80000000u) ? ~b : (b | 0x80000000u);
}
__device__ __forceinline__ float fkey_inv(unsigned k) {
    return (k & 0x80000000u) ? __uint_as_float(k ^ 0x80000000u)
                             : __uint_as_float(~k);
}

// byte offset of bf16 element (row, ke) in a [128][256] tile with
// per-row XOR swizzle on 16B chunks (c in 0..31, low 3 bits XOR row&7)
__device__ __forceinline__ uint32_t tile_off(int row, int ke) {
    int c = ke >> 3;
    return (uint32_t)(row * 512 + (((c & 24) | ((c ^ row) & 7)) << 4) + (ke & 7) * 2);
}

__device__ __forceinline__ void mma_bf16(float* c, uint32_t a0, uint32_t a1,
                                         uint32_t a2, uint32_t a3,
                                         uint32_t b0, uint32_t b1) {
    asm("mma.sync.aligned.m16n8k16.row.col.f32.bf16.bf16.f32 "
        "{%0,%1,%2,%3}, {%4,%5,%6,%7}, {%8,%9}, {%0,%1,%2,%3};"
        : "+f"(c[0]), "+f"(c[1]), "+f"(c[2]), "+f"(c[3])
        : "r"(a0), "r"(a1), "r"(a2), "r"(a3), "r"(b0), "r"(b1));
}

// ---------------- kernel 1: zero scratch + copy x to output ----------------
__global__ void k_init(const float4* __restrict__ x4, float4* __restrict__ out4) {
    int i = blockIdx.x * 256 + threadIdx.x;
    if (i < NN * DD / 4) out4[i] = x4[i];
    if (i < NN) {
        g_negsum[i] = 0.f;
        g_poslog[i] = 0.f;
        g_poscnt[i] = 0;
        g_minsimi[i] = 0x7F800000u;
    }
    if (i == 0) {
        g_maxdist_u = 0u;
        g_maxedge_u = 0u;
        g_minedge_u = 0xFFFFFFFFu;
        g_loss = 0.f;
    }
}

// pack two fp32 -> {hi bf16 pair, lo bf16 pair}
__device__ __forceinline__ void split2(float v0, float v1, uint32_t& hi, uint32_t& lo) {
    __nv_bfloat16 h0 = __float2bfloat16(v0);
    __nv_bfloat16 h1 = __float2bfloat16(v1);
    __nv_bfloat16 l0 = __float2bfloat16(v0 - __bfloat162float(h0));
    __nv_bfloat16 l1 = __float2bfloat16(v1 - __bfloat162float(h1));
    hi = (uint32_t)__bfloat16_as_ushort(h0) | ((uint32_t)__bfloat16_as_ushort(h1) << 16);
    lo = (uint32_t)__bfloat16_as_ushort(l0) | ((uint32_t)__bfloat16_as_ushort(l1) << 16);
}

// ---------------- kernel 2: split-bf16 mma.sync GEMM + epilogue ----------------
__global__ __launch_bounds__(256, 1)
void k_main(const float* __restrict__ x, const int* __restrict__ adj,
            float* __restrict__ dist) {
    extern __shared__ char smem[];
    const int tid = threadIdx.x;
    const int wid = tid >> 5;
    const int lane = tid & 31;
    const int rowBase = blockIdx.y * 128;
    const int colBase = blockIdx.x * 128;

    float* sX0r = (float*)(smem + SM_X0R);
    float* sX0c = (float*)(smem + SM_X0C);
    if (tid < 128)       sX0r[tid]       = x[(size_t)(rowBase + tid) * DD];
    else                 sX0c[tid - 128] = x[(size_t)(colBase + tid - 128) * DD];

    // ---- load tiles, split fp32 -> bf16 hi/lo, store swizzled ----
    // A2[row][k]: k<128 = hi, k>=128 = lo.   B2[col][k]: k<128 = lo, k>=128 = hi.
#pragma unroll
    for (int it = 0; it < 16; ++it) {
        int idx = tid + it * 256;     // 0..4095 float4 slots
        int row = idx >> 5;
        int q   = idx & 31;           // float4 index along K (0..31)
        float4 va = *reinterpret_cast<const float4*>(&x[(size_t)(rowBase + row) * DD + q * 4]);
        float4 vb = *reinterpret_cast<const float4*>(&x[(size_t)(colBase + row) * DD + q * 4]);
        if (q == 0) { va.x = 0.f; vb.x = 0.f; }   // drop d==0; exact in epilogue

        uint2 ah, al, bh, bl;
        split2(va.x, va.y, ah.x, al.x); split2(va.z, va.w, ah.y, al.y);
        split2(vb.x, vb.y, bh.x, bl.x); split2(vb.z, vb.w, bh.y, bl.y);

        uint32_t off0 = tile_off(row, q * 4);          // chunk in first K-half
        uint32_t off1 = tile_off(row, q * 4 + 128);    // chunk in second K-half
        *reinterpret_cast<uint2*>(smem + SM_A + off0) = ah;   // A hi
        *reinterpret_cast<uint2*>(smem + SM_A + off1) = al;   // A lo
        *reinterpret_cast<uint2*>(smem + SM_B + off0) = bl;   // B lo
        *reinterpret_cast<uint2*>(smem + SM_B + off1) = bh;   // B hi
    }
    __syncthreads();

    // ---- warp-tiled mma: warp = 64x32 region ----
    const int warp_m = (wid & 1) * 64;
    const int warp_n = (wid >> 1) * 32;
    const int lq = lane >> 2;          // 0..7
    const int kq = (lane & 3) * 2;     // 0,2,4,6

    float acc[16][4];
#pragma unroll
    for (int t = 0; t < 16; ++t)
#pragma unroll
        for (int j = 0; j < 4; ++j) acc[t][j] = 0.f;

    for (int ks = 0; ks < 24; ++ks) {
        // pass mapping: ks<16 -> cross (A[hi|lo] x B[lo|hi], K=256);
        //               ks>=16 -> hi*hi (A first half x B second half)
        int kA = (ks < 16 ? ks : ks - 16) * 16;
        int kB = (ks < 16 ? ks : ks - 8) * 16;

        uint32_t afr[4][4], bfr[4][2];
#pragma unroll
        for (int t = 0; t < 4; ++t) {
            int r = warp_m + t * 16 + lq;
            afr[t][0] = *reinterpret_cast<uint32_t*>(smem + SM_A + tile_off(r,     kA + kq));
            afr[t][1] = *reinterpret_cast<uint32_t*>(smem + SM_A + tile_off(r + 8, kA + kq));
            afr[t][2] = *reinterpret_cast<uint32_t*>(smem + SM_A + tile_off(r,     kA + kq + 8));
            afr[t][3] = *reinterpret_cast<uint32_t*>(smem + SM_A + tile_off(r + 8, kA + kq + 8));
        }
#pragma unroll
        for (int u = 0; u < 4; ++u) {
            int ccol = warp_n + u * 8 + lq;
            bfr[u][0] = *reinterpret_cast<uint32_t*>(smem + SM_B + tile_off(ccol, kB + kq));
            bfr[u][1] = *reinterpret_cast<uint32_t*>(smem + SM_B + tile_off(ccol, kB + kq + 8));
        }
#pragma unroll
        for (int t = 0; t < 4; ++t)
#pragma unroll
            for (int u = 0; u < 4; ++u)
                mma_bf16(acc[t * 4 + u], afr[t][0], afr[t][1], afr[t][2], afr[t][3],
                         bfr[u][0], bfr[u][1]);
    }
    __syncthreads();   // all warps done reading tiles before sD overwrites them

    // ---- stage C into smem (plain [128][132] fp32) ----
    float* sD = (float*)(smem + SM_D);
#pragma unroll
    for (int t = 0; t < 4; ++t) {
#pragma unroll
        for (int u = 0; u < 4; ++u) {
            int r = warp_m + t * 16 + lq;
            int cc = warp_n + u * 8 + kq;
            *reinterpret_cast<float2*>(&sD[r * SD_LD + cc]) =
                make_float2(acc[t * 4 + u][0], acc[t * 4 + u][1]);
            *reinterpret_cast<float2*>(&sD[(r + 8) * SD_LD + cc]) =
                make_float2(acc[t * 4 + u][2], acc[t * 4 + u][3]);
        }
    }
    __syncthreads();

    // ---- fused epilogue (identical math to round 1, + exact -x0_i*x0_j) ----
    const int tx = tid & 15;
    const int ty = tid >> 4;
    float locMaxD = 0.f;
    float locMaxE = -INFINITY, locMinE = INFINITY;

    float x0c8[8];
    {
        float4 c0 = *reinterpret_cast<const float4*>(&sX0c[tx * 8]);
        float4 c1 = *reinterpret_cast<const float4*>(&sX0c[tx * 8 + 4]);
        x0c8[0]=c0.x; x0c8[1]=c0.y; x0c8[2]=c0.z; x0c8[3]=c0.w;
        x0c8[4]=c1.x; x0c8[5]=c1.y; x0c8[6]=c1.z; x0c8[7]=c1.w;
    }

#pragma unroll
    for (int i = 0; i < 8; i++) {
        int row = ty * 8 + i;
        int gRow = rowBase + row;
        float x0i = sX0r[row];

        const int* arow = &adj[(size_t)gRow * NN + colBase + tx * 8];
        int4 aj0 = *reinterpret_cast<const int4*>(arow);
        int4 aj1 = *reinterpret_cast<const int4*>(arow + 4);
        int av[8] = {aj0.x, aj0.y, aj0.z, aj0.w, aj1.x, aj1.y, aj1.z, aj1.w};

        float cv[8];
        {
            float4 d0 = *reinterpret_cast<const float4*>(&sD[row * SD_LD + tx * 8]);
            float4 d1 = *reinterpret_cast<const float4*>(&sD[row * SD_LD + tx * 8 + 4]);
            cv[0]=d0.x; cv[1]=d0.y; cv[2]=d0.z; cv[3]=d0.w;
            cv[4]=d1.x; cv[5]=d1.y; cv[6]=d1.z; cv[7]=d1.w;
        }

        float dv[8];
        float neg = 0.f, plog = 0.f, msimi = INFINITY;
        int pcnt = 0;
#pragma unroll
        for (int j = 0; j < 8; j++) {
            float c = cv[j] - x0i * x0c8[j];           // exact Minkowski inner
            float theta = fmaxf(-c, 1.0f + 1e-7f);
            float sq = sqrtf((theta - 1.0f) * (theta + 1.0f));
            float ac = __logf(theta + sq);
            float d = fminf(ac * ac, 50.0f);
            dv[j] = d;
            locMaxD = fmaxf(locMaxD, d);
            float simi = fmaxf(__expf(-d), 1e-15f);
            if (av[j] != 0) {
                pcnt++;
                plog += fmaxf(-d, -34.538776394910684f);
                msimi = fminf(msimi, simi);
                locMaxE = fmaxf(locMaxE, c);
                locMinE = fminf(locMinE, c);
            } else {
                neg += simi;
                locMaxE = fmaxf(locMaxE, 0.f);
                locMinE = fminf(locMinE, 0.f);
            }
        }
        float* drow = &dist[(size_t)gRow * NN + colBase + tx * 8];
        *reinterpret_cast<float4*>(drow)     = make_float4(dv[0], dv[1], dv[2], dv[3]);
        *reinterpret_cast<float4*>(drow + 4) = make_float4(dv[4], dv[5], dv[6], dv[7]);

#pragma unroll
        for (int off = 1; off < 16; off <<= 1) {
            neg  += __shfl_xor_sync(0xffffffffu, neg,  off);
            plog += __shfl_xor_sync(0xffffffffu, plog, off);
            pcnt += __shfl_xor_sync(0xffffffffu, pcnt, off);
            msimi = fminf(msimi, __shfl_xor_sync(0xffffffffu, msimi, off));
        }
        if (tx == 0) {
            atomicAdd(&g_negsum[gRow], neg);
            atomicAdd(&g_poslog[gRow], plog);
            atomicAdd(&g_poscnt[gRow], pcnt);
            atomicMin(&g_minsimi[gRow], __float_as_uint(msimi));
        }
    }

#pragma unroll
    for (int off = 16; off > 0; off >>= 1) {
        locMaxD = fmaxf(locMaxD, __shfl_xor_sync(0xffffffffu, locMaxD, off));
        locMaxE = fmaxf(locMaxE, __shfl_xor_sync(0xffffffffu, locMaxE, off));
        locMinE = fminf(locMinE, __shfl_xor_sync(0xffffffffu, locMinE, off));
    }
    __shared__ float red[3][8];
    if (lane == 0) { red[0][wid] = locMaxD; red[1][wid] = locMaxE; red[2][wid] = locMinE; }
    __syncthreads();
    if (tid == 0) {
        float md = red[0][0], me = red[1][0], mn = red[2][0];
#pragma unroll
        for (int i = 1; i < 8; i++) {
            md = fmaxf(md, red[0][i]);
            me = fmaxf(me, red[1][i]);
            mn = fminf(mn, red[2][i]);
        }
        atomicMax(&g_maxdist_u, fkey(md));
        atomicMax(&g_maxedge_u, fkey(me));
        atomicMin(&g_minedge_u, fkey(mn));
    }
}

// ---------------- kernel 3: per-row loss finalize ----------------
__global__ void k_finalize(const float* __restrict__ dist, const int* __restrict__ adj) {
    int row = blockIdx.x;
    int cnt = g_poscnt[row];
    if (cnt == 0) return;
    float ns = g_negsum[row];
    float msimi = __uint_as_float(g_minsimi[row]);
    bool clampFree = (ns > 0.f) && (msimi >= 1e-15f * ns);
    if (clampFree) {
        if (threadIdx.x == 0) {
            float li = -(g_poslog[row] - (float)cnt * __logf(ns));
            atomicAdd(&g_loss, li);
        }
        return;
    }
    float part = 0.f;
    for (int j = threadIdx.x; j < NN; j += blockDim.x) {
        if (adj[(size_t)row * NN + j]) {
            float d = dist[(size_t)row * NN + j];
            float simi = fmaxf(__expf(-d), 1e-15f);
            float ratio = fmaxf(simi / ns, 1e-15f);
            part += __logf(ratio);
        }
    }
#pragma unroll
    for (int off = 16; off > 0; off >>= 1)
        part += __shfl_xor_sync(0xffffffffu, part, off);
    __shared__ float sred[8];
    int w = threadIdx.x >> 5, l = threadIdx.x & 31;
    if (l == 0) sred[w] = part;
    __syncthreads();
    if (threadIdx.x == 0) {
        float s = 0.f;
        for (int i = 0; i < (int)blockDim.x / 32; i++) s += sred[i];
        atomicAdd(&g_loss, -s);
    }
}

// ---------------- kernel 4: scalars ----------------
__global__ void k_scalars(float* __restrict__ outsc) {
    outsc[0] = g_loss;
    outsc[1] = fkey_inv(g_maxdist_u);
    outsc[2] = fkey_inv(g_maxedge_u);
    outsc[3] = fkey_inv(g_minedge_u);
}

// ---------------- launch ----------------
extern "C" void kernel_launch(void* const* d_in, const int* in_sizes, int n_in,
                              void* d_out, int out_size) {
    const float* x  = (const float*)d_in[0];
    const int* adj  = (const int*)d_in[1];
    float* out = (float*)d_out;

    size_t distOff = (size_t)out_size - 4 - (size_t)NN * NN;
    float* dist  = out + distOff;
    float* outsc = out + ((size_t)out_size - 4);

    cudaFuncSetAttribute(k_main, cudaFuncAttributeMaxDynamicSharedMemorySize, SM_TOTAL);

    k_init<<<(NN * DD / 4 + 255) / 256, 256>>>((const float4*)x, (float4*)out);
    dim3 grid(NN / 128, NN / 128);
    k_main<<<grid, 256, SM_TOTAL>>>(x, adj, dist);
    k_finalize<<<NN, 256>>>(dist, adj);
    k_scalars<<<1, 1>>>(outsc);
}